// round 13
// baseline (speedup 1.0000x reference)
#include <cuda_runtime.h>
#include <cuda_bf16.h>
#include <cstdint>

// ---------------- problem shape (fixed) ----------------
constexpr int BN = 8, LN = 1024, SN = 1024, HN = 16, EN = 64, DN = 64;

constexpr int MQ  = 64;            // queries per CTA
constexpr int NK  = 64;            // keys per chunk
constexpr int NCH = SN / NK;       // 16
constexpr int NTHREADS = 256;      // 8 warps
constexpr int CAPQ = 24;           // candidate capacity per (row, quarter)

constexpr int Z_STRIDE  = 76;      // f32 per z row

// ---------------- smem layout (bytes) ----------------
constexpr int QTILE   = MQ * 144;                  // 9216 (hi or lo)
constexpr int OFF_QHI = 0;
constexpr int OFF_QLO = QTILE;                     // 9216
constexpr int OFF_KB  = 2 * QTILE;                 // 18432 ; 2 buffers
constexpr int KTILE   = NK * 144;                  // 9216
constexpr int KBUF    = 2 * KTILE;                 // hi+lo = 18432
constexpr int OFF_Z   = OFF_KB + 2 * KBUF;         // 55296
constexpr int OFF_CV  = OFF_Z + MQ * Z_STRIDE * 4; // 74752 ; float[64*4*CAPQ]
constexpr int OFF_CI  = OFF_CV + MQ * 4 * CAPQ * 4;// 99328 ; u16
constexpr int OFF_CNT = OFF_CI + MQ * 4 * CAPQ * 2;// 111616 ; int[256]
constexpr int SMEM_BYTES = OFF_CNT + MQ * 4 * 4;   // 112640 (110 KB -> 2 CTAs/SM)

// ---------------- prepped bf16 hi/lo tensors ([b][h][l|s][e]) ----------------
__device__ __nv_bfloat16 g_qhi[(size_t)BN*HN*LN*EN];
__device__ __nv_bfloat16 g_qlo[(size_t)BN*HN*LN*EN];
__device__ __nv_bfloat16 g_khi[(size_t)BN*HN*SN*EN];
__device__ __nv_bfloat16 g_klo[(size_t)BN*HN*SN*EN];

// ---------------- PTX helpers ----------------
__device__ __forceinline__ uint32_t smem_to_u32(const void* p) {
    uint32_t a;
    asm("{ .reg .u64 t; cvta.to.shared.u64 t, %1; cvt.u32.u64 %0, t; }" : "=r"(a) : "l"(p));
    return a;
}
__device__ __forceinline__ void ldsm_x4(uint32_t r[4], uint32_t addr) {
    asm volatile("ldmatrix.sync.aligned.m8n8.x4.shared.b16 {%0,%1,%2,%3}, [%4];"
                 : "=r"(r[0]), "=r"(r[1]), "=r"(r[2]), "=r"(r[3]) : "r"(addr));
}
__device__ __forceinline__ void mma_bf16(float d[4], const uint32_t a[4],
                                         uint32_t b0, uint32_t b1) {
    asm volatile("mma.sync.aligned.m16n8k16.row.col.f32.bf16.bf16.f32 "
                 "{%0,%1,%2,%3}, {%4,%5,%6,%7}, {%8,%9}, {%0,%1,%2,%3};"
                 : "+f"(d[0]), "+f"(d[1]), "+f"(d[2]), "+f"(d[3])
                 : "r"(a[0]), "r"(a[1]), "r"(a[2]), "r"(a[3]), "r"(b0), "r"(b1));
}

// ---------------- prep: fp32 -> bf16 hi/lo, [b,l,h,e] -> [b,h,l,e] ----------------
__global__ void prep_kernel(const float* __restrict__ Q, const float* __restrict__ K) {
    const size_t total = (size_t)BN * LN * HN * EN;
    for (size_t i = (size_t)blockIdx.x * blockDim.x + threadIdx.x; i < total;
         i += (size_t)gridDim.x * blockDim.x) {
        const int e = (int)(i & 63);
        const int h = (int)((i >> 6) & 15);
        const int l = (int)((i >> 10) & 1023);
        const int b = (int)(i >> 20);
        const size_t o = ((((size_t)b * HN + h) * LN + l) << 6) + e;

        float q = Q[i] * 0.125f;                        // fold 1/sqrt(E)
        __nv_bfloat16 qh = __float2bfloat16(q);
        g_qhi[o] = qh;
        g_qlo[o] = __float2bfloat16(q - __bfloat162float(qh));

        float k = K[i];
        __nv_bfloat16 kh = __float2bfloat16(k);
        g_khi[o] = kh;
        g_klo[o] = __float2bfloat16(k - __bfloat162float(kh));
    }
}

// ---------------- main kernel ----------------
__global__ __launch_bounds__(NTHREADS, 2)
void sparsemax_attn_mma(const float* __restrict__ V, float* __restrict__ O) {
    extern __shared__ char smem[];
    const uint32_t sb = smem_to_u32(smem);
    const int tid = threadIdx.x, lane = tid & 31, warp = tid >> 5;
    const int wq = warp & 1, wk = warp >> 1;        // 2 q-groups x 4 k-groups
    const int l0 = blockIdx.x * MQ, h = blockIdx.y, b = blockIdx.z;
    const size_t bh = (size_t)b * HN + h;

    // ---- stage Q hi/lo into padded smem tiles (512 slots, 2 per thread) ----
    {
        const uint4* qh = reinterpret_cast<const uint4*>(g_qhi + ((bh * LN + l0) << 6));
        const uint4* ql = reinterpret_cast<const uint4*>(g_qlo + ((bh * LN + l0) << 6));
        #pragma unroll
        for (int p = 0; p < 2; ++p) {
            const int slot = tid + NTHREADS * p;
            const int dst = (slot >> 3) * 144 + (slot & 7) * 16;
            *reinterpret_cast<uint4*>(smem + OFF_QHI + dst) = qh[slot];
            *reinterpret_cast<uint4*>(smem + OFF_QLO + dst) = ql[slot];
        }
    }

    // ---- stage K chunk 0 (512 slots per hi/lo, 2 per thread) ----
    const uint4* gkh = reinterpret_cast<const uint4*>(g_khi + ((bh * SN) << 6));
    const uint4* gkl = reinterpret_cast<const uint4*>(g_klo + ((bh * SN) << 6));
    const int d0 = (tid >> 3) * 144 + (tid & 7) * 16;   // row tid>>3 (0..31)
    const int d1 = d0 + 32 * 144;                        // row +32
    {
        *reinterpret_cast<uint4*>(smem + OFF_KB + d0) = gkh[tid];
        *reinterpret_cast<uint4*>(smem + OFF_KB + d1) = gkh[tid + 256];
        *reinterpret_cast<uint4*>(smem + OFF_KB + KTILE + d0) = gkl[tid];
        *reinterpret_cast<uint4*>(smem + OFF_KB + KTILE + d1) = gkl[tid + 256];
    }
    __syncthreads();

    // ---- ldmatrix lane addressing ----
    const int lrow  = lane & 15;
    const int lhalf = (lane >> 4) * 16;

    // cache A-hi fragments for the whole CTA lifetime: [mt][ks][4]
    uint32_t ah[2][4][4];
    uint32_t qloA[2];  // per-mt base addrs for A-lo reloads
    #pragma unroll
    for (int mt = 0; mt < 2; ++mt) {
        const uint32_t rowoff = (uint32_t)(32 * wq + 16 * mt + lrow) * 144 + lhalf;
        qloA[mt] = sb + OFF_QLO + rowoff;
        #pragma unroll
        for (int ks = 0; ks < 4; ++ks)
            ldsm_x4(ah[mt][ks], sb + OFF_QHI + rowoff + 32 * ks);
    }

    // per-lane candidate state: row = warp*8 + (lane>>2), quarter = lane&3
    const int rsub = lane >> 2, t4 = lane & 3;
    const int myrow = warp * 8 + rsub;
    float runmax = -1e30f;
    float thr    = -1e30f;   // max(runmax-1, streaming tau lower bound)
    float csum   = 0.f;      // sum of current candidates (this lane's list)
    int cnt = 0;
    float* cv = reinterpret_cast<float*>(smem + OFF_CV) + (myrow * 4 + t4) * CAPQ;
    uint16_t* cix = reinterpret_cast<uint16_t*>(smem + OFF_CI) + (myrow * 4 + t4) * CAPQ;

    const uint32_t kbRow = (uint32_t)(16 * wk + lrow) * 144 + lhalf;
    const int g = lane >> 2, tt = lane & 3;

    // scan of z for chunk cc — two passes (max, then reload+insert) to cap regs.
    const float* zlane = reinterpret_cast<const float*>(smem + OFF_Z)
                         + (size_t)myrow * Z_STRIDE + 16 * t4;
    auto scan_chunk = [&](int cc) {
        // pass 1: block max
        float bmax = -1e30f;
        #pragma unroll
        for (int i = 0; i < 4; ++i) {
            const float4 f = reinterpret_cast<const float4*>(zlane)[i];
            bmax = fmaxf(bmax, fmaxf(fmaxf(f.x, f.y), fmaxf(f.z, f.w)));
        }
        bmax = fmaxf(bmax, __shfl_xor_sync(0xffffffffu, bmax, 1));
        bmax = fmaxf(bmax, __shfl_xor_sync(0xffffffffu, bmax, 2));
        runmax = fmaxf(runmax, bmax);
        thr = fmaxf(thr, runmax - 1.0f);

        // pass 2: reload + insert
        #pragma unroll
        for (int i = 0; i < 4; ++i) {
            const float4 f = reinterpret_cast<const float4*>(zlane)[i];
            float v4[4] = {f.x, f.y, f.z, f.w};
            #pragma unroll
            for (int j = 0; j < 4; ++j) {
                const float v = v4[j];
                if (v > thr) {
                    if (cnt == CAPQ) {       // recompact with freshest thr
                        int m = 0; float s = 0.f;
                        for (int q = 0; q < CAPQ; ++q) {
                            const float cq = cv[q];
                            if (cq > thr) { cv[m] = cq; cix[m] = cix[q]; s += cq; ++m; }
                        }
                        cnt = m; csum = s;
                    }
                    if (cnt < CAPQ) {
                        cv[cnt] = v;
                        cix[cnt] = (uint16_t)(cc * NK + 16 * t4 + 4 * i + j);
                        csum += v;
                        ++cnt;
                    } else {
                        int am = 0; float mn = cv[0];
                        for (int q = 1; q < CAPQ; ++q)
                            if (cv[q] < mn) { mn = cv[q]; am = q; }
                        if (v > mn) {
                            csum += v - mn;
                            cv[am] = v;
                            cix[am] = (uint16_t)(cc * NK + 16 * t4 + 4 * i + j);
                        }
                    }
                }
            }
        }

        // streaming tau lower bound (valid for any subset C of a row:
        // (sum_C - 1)/|C| <= tau*), quad-reduced across the row's 4 lists
        float sq = csum; int cq = cnt;
        sq += __shfl_xor_sync(0xffffffffu, sq, 1);
        sq += __shfl_xor_sync(0xffffffffu, sq, 2);
        cq += __shfl_xor_sync(0xffffffffu, cq, 1);
        cq += __shfl_xor_sync(0xffffffffu, cq, 2);
        if (cq > 0) thr = fmaxf(thr, (sq - 1.0f) / (float)cq);
    };

    for (int c = 0; c < NCH; ++c) {
        const uint32_t kbh = sb + OFF_KB + (c & 1) * KBUF + kbRow;
        const uint32_t kbl = kbh + KTILE;

        float acc[2][2][4];
        #pragma unroll
        for (int mt = 0; mt < 2; ++mt)
            #pragma unroll
            for (int nt = 0; nt < 2; ++nt)
                #pragma unroll
                for (int i = 0; i < 4; ++i) acc[mt][nt][i] = 0.f;

        // ---- issue the chunk's MMAs (tensor pipe goes busy) ----
        #pragma unroll
        for (int ks = 0; ks < 4; ++ks) {
            uint32_t bhf[4], blf[4], al0[4], al1[4];
            ldsm_x4(bhf, kbh + 32 * ks);
            ldsm_x4(blf, kbl + 32 * ks);
            ldsm_x4(al0, qloA[0] + 32 * ks);
            ldsm_x4(al1, qloA[1] + 32 * ks);

            mma_bf16(acc[0][0], ah[0][ks], bhf[0], bhf[2]);
            mma_bf16(acc[0][1], ah[0][ks], bhf[1], bhf[3]);
            mma_bf16(acc[1][0], ah[1][ks], bhf[0], bhf[2]);
            mma_bf16(acc[1][1], ah[1][ks], bhf[1], bhf[3]);

            mma_bf16(acc[0][0], ah[0][ks], blf[0], blf[2]);
            mma_bf16(acc[0][1], ah[0][ks], blf[1], blf[3]);
            mma_bf16(acc[1][0], ah[1][ks], blf[0], blf[2]);
            mma_bf16(acc[1][1], ah[1][ks], blf[1], blf[3]);

            mma_bf16(acc[0][0], al0, bhf[0], bhf[2]);
            mma_bf16(acc[0][1], al0, bhf[1], bhf[3]);
            mma_bf16(acc[1][0], al1, bhf[0], bhf[2]);
            mma_bf16(acc[1][1], al1, bhf[1], bhf[3]);
        }

        // ---- scan previous chunk's z in the tensor shadow ----
        if (c > 0) scan_chunk(c - 1);

        // prefetch next K chunk into registers (hide L2 latency)
        uint4 pfh0, pfh1, pfl0, pfl1;
        if (c + 1 < NCH) {
            const int s0 = (c + 1) * NK * 8 + tid;
            const int s1 = s0 + 256;
            pfh0 = gkh[s0]; pfh1 = gkh[s1];
            pfl0 = gkl[s0]; pfl1 = gkl[s1];
        }

        __syncthreads();   // all warps done scanning z_{c-1}; safe to overwrite

        // ---- write scores to z (accumulators complete by now) ----
        #pragma unroll
        for (int mt = 0; mt < 2; ++mt)
            #pragma unroll
            for (int nt = 0; nt < 2; ++nt) {
                const int row0 = 32 * wq + 16 * mt + g;
                const int col  = 16 * wk + 8 * nt + 2 * tt;
                float2 lo2; lo2.x = acc[mt][nt][0]; lo2.y = acc[mt][nt][1];
                float2 hi2; hi2.x = acc[mt][nt][2]; hi2.y = acc[mt][nt][3];
                *reinterpret_cast<float2*>(smem + OFF_Z + ((size_t)row0 * Z_STRIDE + col) * 4) = lo2;
                *reinterpret_cast<float2*>(smem + OFF_Z + ((size_t)(row0 + 8) * Z_STRIDE + col) * 4) = hi2;
            }

        // ---- stage prefetched chunk into the other buffer ----
        if (c + 1 < NCH) {
            char* kb = smem + OFF_KB + ((c + 1) & 1) * KBUF;
            *reinterpret_cast<uint4*>(kb + d0) = pfh0;
            *reinterpret_cast<uint4*>(kb + d1) = pfh1;
            *reinterpret_cast<uint4*>(kb + KTILE + d0) = pfl0;
            *reinterpret_cast<uint4*>(kb + KTILE + d1) = pfl1;
        }
        __syncthreads();   // z_c visible; next K buffer ready
    }

    // ---- tail: scan the last chunk's z ----
    scan_chunk(NCH - 1);

    // ---- quad-cooperative Michelot tau (exact on candidate superset) ----
    {
        float s = csum;
        s += __shfl_xor_sync(0xffffffffu, s, 1);
        s += __shfl_xor_sync(0xffffffffu, s, 2);
        int ctot = cnt;
        ctot += __shfl_xor_sync(0xffffffffu, ctot, 1);
        ctot += __shfl_xor_sync(0xffffffffu, ctot, 2);
        float tau = (s - 1.0f) / (float)ctot;

        bool changed = true;
        while (__any_sync(0xffffffffu, changed)) {
            float s2 = 0.f; int c2 = 0;
            for (int i = 0; i < cnt; ++i) {
                const float vv = cv[i];
                if (vv > tau) { s2 += vv; ++c2; }
            }
            s2 += __shfl_xor_sync(0xffffffffu, s2, 1);
            s2 += __shfl_xor_sync(0xffffffffu, s2, 2);
            c2 += __shfl_xor_sync(0xffffffffu, c2, 1);
            c2 += __shfl_xor_sync(0xffffffffu, c2, 2);
            const float tn = (s2 - 1.0f) / (float)c2;
            changed = (tn > tau);
            if (changed) tau = tn;
        }

        // compact to p = v - tau > 0
        int m = 0;
        for (int i = 0; i < cnt; ++i) {
            const float vv = cv[i];
            if (vv > tau) { cv[m] = vv - tau; cix[m] = cix[i]; ++m; }
        }
        reinterpret_cast<int*>(smem + OFF_CNT)[myrow * 4 + t4] = m;
    }
    __syncthreads();

    // ---- sparse AV: warp w -> rows 8w..8w+7; lane covers d=lane, lane+32 ----
    {
        const float* vb = V + ((size_t)b * SN * HN + h) * DN;
        const int* scnt = reinterpret_cast<const int*>(smem + OFF_CNT);
        for (int rr = 0; rr < 8; ++rr) {
            const int row = warp * 8 + rr;
            float o0 = 0.f, o1 = 0.f;
            #pragma unroll
            for (int t = 0; t < 4; ++t) {
                const int m = scnt[row * 4 + t];
                const float* cvr = reinterpret_cast<const float*>(smem + OFF_CV)
                                   + (row * 4 + t) * CAPQ;
                const uint16_t* cir = reinterpret_cast<const uint16_t*>(smem + OFF_CI)
                                   + (row * 4 + t) * CAPQ;
                for (int i = 0; i < m; ++i) {
                    const float p = cvr[i];
                    const int j = cir[i];
                    const float* vr = vb + (size_t)j * HN * DN;
                    o0 += p * vr[lane];
                    o1 += p * vr[lane + 32];
                }
            }
            float* orow = O + (((size_t)b * LN + l0 + row) * HN + h) * DN;
            orow[lane]      = o0;
            orow[lane + 32] = o1;
        }
    }
}

// ---------------- launch ----------------
extern "C" void kernel_launch(void* const* d_in, const int* in_sizes, int n_in,
                              void* d_out, int out_size) {
    const float* Q = (const float*)d_in[0];
    const float* K = (const float*)d_in[1];
    const float* V = (const float*)d_in[2];
    float* O = (float*)d_out;

    prep_kernel<<<4096, 256>>>(Q, K);

    cudaFuncSetAttribute(sparsemax_attn_mma,
                         cudaFuncAttributeMaxDynamicSharedMemorySize, SMEM_BYTES);
    dim3 grid(LN / MQ, HN, BN);
    sparsemax_attn_mma<<<grid, NTHREADS, SMEM_BYTES>>>(V, O);
}